// round 1
// baseline (speedup 1.0000x reference)
#include <cuda_runtime.h>
#include <math.h>

#define B_  64
#define S_  64
#define F_  2048
#define H_  512
#define G4_ 2048
#define P_  20
#define R_  4096   // B*S

// ---------------- scratch (static device globals; no allocs) ----------------
__device__ float g_fuse[R_ * H_];        // [B*S, H]   8 MB
__device__ float g_xg[S_ * B_ * G4_];    // [S][B][4H] 32 MB
__device__ float g_hbuf[2][B_ * H_];     // double-buffered hidden state
__device__ float g_c[B_ * H_];           // cell state (in-place, column-disjoint per block)
__device__ float g_ddp[B_ * S_];         // per-(b,s) prototype partial
__device__ int   g_cat[B_];              // normalized category

__device__ __forceinline__ float sigmoidf_(float x) { return 1.0f / (1.0f + expf(-x)); }

// ---------------- category dtype normalization (int64 vs int32) -------------
__global__ void cat_normalize(const int* __restrict__ w) {
    if (threadIdx.x == 0 && blockIdx.x == 0) {
        bool oddzero = true, evenok = true;
        for (int i = 0; i < 32; i++) {
            int lo = w[2 * i], hi = w[2 * i + 1];
            if (hi != 0) oddzero = false;
            if (lo < 0 || lo > 2) evenok = false;
        }
        if (oddzero && evenok) {  // little-endian int64 layout
            const long long* c = (const long long*)w;
            for (int b = 0; b < B_; b++) g_cat[b] = (int)c[b];
        } else {                  // int32 layout
            for (int b = 0; b < B_; b++) g_cat[b] = w[b];
        }
    }
}

// ---------------- zero h0 / c0 ----------------------------------------------
__global__ void init_state() {
    int idx = blockIdx.x * blockDim.x + threadIdx.x;
    if (idx < B_ * H_) { g_hbuf[0][idx] = 0.0f; g_c[idx] = 0.0f; }
}

// ---------------- fuse = relu(v @ W_enc + b_enc) + cat_emb[cat] --------------
// M=4096, N=512, K=2048. 128x128 tile, BK=8, 256 threads, 8x8 micro.
__global__ __launch_bounds__(256) void fuse_gemm(
    const float* __restrict__ A, const float* __restrict__ W,
    const float* __restrict__ bias, const float* __restrict__ cat_emb)
{
    __shared__ float As[8][132];
    __shared__ float Bs[8][128];
    const int tid  = threadIdx.x;
    const int brow = blockIdx.y * 128;
    const int bcol = blockIdx.x * 128;
    const int a_r = tid >> 1, a_c = (tid & 1) * 4;
    const int b_r = tid >> 5, b_c = (tid & 31) * 4;
    const int trow = (tid >> 4) * 8, tcol = (tid & 15) * 8;
    const int K = F_, N = H_;

    float acc[8][8];
    #pragma unroll
    for (int i = 0; i < 8; i++)
        #pragma unroll
        for (int j = 0; j < 8; j++) acc[i][j] = 0.0f;

    for (int k0 = 0; k0 < K; k0 += 8) {
        float4 av = *reinterpret_cast<const float4*>(&A[(size_t)(brow + a_r) * K + k0 + a_c]);
        As[a_c + 0][a_r] = av.x; As[a_c + 1][a_r] = av.y;
        As[a_c + 2][a_r] = av.z; As[a_c + 3][a_r] = av.w;
        float4 bv = *reinterpret_cast<const float4*>(&W[(size_t)(k0 + b_r) * N + bcol + b_c]);
        *reinterpret_cast<float4*>(&Bs[b_r][b_c]) = bv;
        __syncthreads();
        #pragma unroll
        for (int k = 0; k < 8; k++) {
            float ar[8], br[8];
            #pragma unroll
            for (int i = 0; i < 8; i++) ar[i] = As[k][trow + i];
            #pragma unroll
            for (int j = 0; j < 8; j++) br[j] = Bs[k][tcol + j];
            #pragma unroll
            for (int i = 0; i < 8; i++)
                #pragma unroll
                for (int j = 0; j < 8; j++) acc[i][j] = fmaf(ar[i], br[j], acc[i][j]);
        }
        __syncthreads();
    }
    #pragma unroll
    for (int i = 0; i < 8; i++) {
        int r = brow + trow + i;
        int b = r >> 6;
        const float* ce = &cat_emb[g_cat[b] * H_];
        #pragma unroll
        for (int j = 0; j < 8; j++) {
            int n = bcol + tcol + j;
            float v = acc[i][j] + bias[n];
            v = fmaxf(v, 0.0f) + ce[n];
            g_fuse[(size_t)r * H_ + n] = v;
        }
    }
}

// ---------------- x_gates[s][b][g] = fuse @ Wx + (bx+bh) ---------------------
// M=4096, N=2048, K=512.
__global__ __launch_bounds__(256) void xg_gemm(
    const float* __restrict__ W, const float* __restrict__ bx,
    const float* __restrict__ bh)
{
    __shared__ float As[8][132];
    __shared__ float Bs[8][128];
    const int tid  = threadIdx.x;
    const int brow = blockIdx.y * 128;
    const int bcol = blockIdx.x * 128;
    const int a_r = tid >> 1, a_c = (tid & 1) * 4;
    const int b_r = tid >> 5, b_c = (tid & 31) * 4;
    const int trow = (tid >> 4) * 8, tcol = (tid & 15) * 8;
    const int K = H_, N = G4_;

    float acc[8][8];
    #pragma unroll
    for (int i = 0; i < 8; i++)
        #pragma unroll
        for (int j = 0; j < 8; j++) acc[i][j] = 0.0f;

    for (int k0 = 0; k0 < K; k0 += 8) {
        float4 av = *reinterpret_cast<const float4*>(&g_fuse[(size_t)(brow + a_r) * K + k0 + a_c]);
        As[a_c + 0][a_r] = av.x; As[a_c + 1][a_r] = av.y;
        As[a_c + 2][a_r] = av.z; As[a_c + 3][a_r] = av.w;
        float4 bv = *reinterpret_cast<const float4*>(&W[(size_t)(k0 + b_r) * N + bcol + b_c]);
        *reinterpret_cast<float4*>(&Bs[b_r][b_c]) = bv;
        __syncthreads();
        #pragma unroll
        for (int k = 0; k < 8; k++) {
            float ar[8], br[8];
            #pragma unroll
            for (int i = 0; i < 8; i++) ar[i] = As[k][trow + i];
            #pragma unroll
            for (int j = 0; j < 8; j++) br[j] = Bs[k][tcol + j];
            #pragma unroll
            for (int i = 0; i < 8; i++)
                #pragma unroll
                for (int j = 0; j < 8; j++) acc[i][j] = fmaf(ar[i], br[j], acc[i][j]);
        }
        __syncthreads();
    }
    #pragma unroll
    for (int i = 0; i < 8; i++) {
        int r = brow + trow + i;
        int bb = r >> 6, ss = r & 63;
        size_t base = ((size_t)(ss * B_ + bb)) * G4_;
        #pragma unroll
        for (int j = 0; j < 8; j++) {
            int n = bcol + tcol + j;
            g_xg[base + n] = acc[i][j] + bx[n] + bh[n];
        }
    }
}

// ---------------- one LSTM step: gates = xg[s] + h @ Wh; fused cell update ---
// Grid: 128 blocks, block b owns hidden cols [4b, 4b+4) across all 4 gates.
// GEMM tile: 64 rows x 16 cols (4 gates x 4 j), K=512, BK=16, 256 threads.
__global__ __launch_bounds__(256) void lstm_step(const float* __restrict__ Wh, int s)
{
    __shared__ float As[16][68];   // h tile, transposed; stride 68 (272B, 16B-aligned)
    __shared__ float Bs[16][16];
    __shared__ float Gs[64][17];   // computed gates

    const float* __restrict__ h_in = g_hbuf[s & 1];
    float* __restrict__ h_out      = g_hbuf[(s + 1) & 1];
    const float* __restrict__ xg_s = &g_xg[(size_t)s * B_ * G4_];

    const int tid   = threadIdx.x;
    const int jbase = blockIdx.x * 4;
    const int a_r = tid >> 2, a_c = (tid & 3) * 4;
    const int b_k = tid >> 4, b_n = tid & 15;
    const int wh_col = (b_n >> 2) * H_ + jbase + (b_n & 3);
    const int trow = (tid >> 4) * 4, tcol = tid & 15;

    float acc[4] = {0.0f, 0.0f, 0.0f, 0.0f};

    for (int k0 = 0; k0 < H_; k0 += 16) {
        float4 av = *reinterpret_cast<const float4*>(&h_in[a_r * H_ + k0 + a_c]);
        As[a_c + 0][a_r] = av.x; As[a_c + 1][a_r] = av.y;
        As[a_c + 2][a_r] = av.z; As[a_c + 3][a_r] = av.w;
        Bs[b_k][b_n] = Wh[(size_t)(k0 + b_k) * G4_ + wh_col];
        __syncthreads();
        #pragma unroll
        for (int k = 0; k < 16; k++) {
            float bv = Bs[k][tcol];
            #pragma unroll
            for (int i = 0; i < 4; i++) acc[i] = fmaf(As[k][trow + i], bv, acc[i]);
        }
        __syncthreads();
    }

    // add precomputed input gates, stash tile
    {
        int gg = tcol >> 2, jl = tcol & 3;
        int ncol = gg * H_ + jbase + jl;
        #pragma unroll
        for (int i = 0; i < 4; i++) {
            int m = trow + i;
            Gs[m][tcol] = acc[i] + xg_s[(size_t)m * G4_ + ncol];
        }
    }
    __syncthreads();

    // cell update: one thread per (batch row, j-col); 64*4 = 256
    {
        int m  = tid >> 2;
        int jl = tid & 3;
        int j  = jbase + jl;
        float iv = Gs[m][0 * 4 + jl];
        float fv = Gs[m][1 * 4 + jl];
        float ov = Gs[m][2 * 4 + jl];
        float gv = Gs[m][3 * 4 + jl];
        float co = g_c[m * H_ + j];
        float cn = sigmoidf_(fv) * co + sigmoidf_(iv) * tanhf(gv);
        float hn = sigmoidf_(ov) * cn;     // NOTE: no tanh on cell in this model
        g_c[m * H_ + j]  = cn;
        h_out[m * H_ + j] = hn;
    }
}

// ---------------- prototype distances -> per-(b,s) W_dd partial --------------
__global__ __launch_bounds__(128) void proto_kernel(
    const float* __restrict__ v, const float* __restrict__ proto,
    const float* __restrict__ W_dd)
{
    const int r = blockIdx.x;          // b*S + s
    const int s = r & 63;
    const int tid = threadIdx.x;
    const float* vrow = &v[(size_t)r * F_];

    float acc[P_];
    #pragma unroll
    for (int p = 0; p < P_; p++) acc[p] = 0.0f;

    for (int f = tid; f < F_; f += 128) {
        float vv = vrow[f];
        #pragma unroll
        for (int p = 0; p < P_; p++) {
            float d = vv - proto[p * F_ + f];
            acc[p] = fmaf(d, d, acc[p]);
        }
    }
    #pragma unroll
    for (int p = 0; p < P_; p++) {
        float x = acc[p];
        #pragma unroll
        for (int o = 16; o > 0; o >>= 1) x += __shfl_down_sync(0xffffffffu, x, o);
        acc[p] = x;
    }
    __shared__ float wsum[4][P_];
    __shared__ float psum[P_];
    int wid = tid >> 5, lane = tid & 31;
    if (lane == 0)
        for (int p = 0; p < P_; p++) wsum[wid][p] = acc[p];
    __syncthreads();
    if (tid < P_) {
        float d = wsum[0][tid] + wsum[1][tid] + wsum[2][tid] + wsum[3][tid];
        float df = logf((d + 1.0f) / (d + 1e-8f));
        psum[tid] = df * W_dd[s * P_ + tid];
    }
    __syncthreads();
    if (tid == 0) {
        float t = 0.0f;
        for (int p = 0; p < P_; p++) t += psum[p];
        g_ddp[r] = t;
    }
}

// ---------------- final combine per batch ------------------------------------
__global__ __launch_bounds__(256) void final_kernel(
    const float* __restrict__ v, const float* __restrict__ W_dec,
    const float* __restrict__ b_dec, const float* __restrict__ W_gate,
    const float* __restrict__ b_gate, const float* __restrict__ b_dd,
    float* __restrict__ out)
{
    const int b = blockIdx.x;
    const int tid = threadIdx.x;

    float hd = 0.0f;
    for (int k = tid; k < H_; k += 256)
        hd += g_hbuf[0][b * H_ + k] * W_dec[k];   // after 64 steps h lives in buf 0

    float gs = 0.0f;
    const float* vb = &v[(size_t)b * S_ * F_];
    for (int idx = tid; idx < S_ * F_; idx += 256)
        gs += vb[idx] * W_gate[idx & (F_ - 1)];

    float ds = 0.0f;
    for (int s = tid; s < S_; s += 256)
        ds += g_ddp[b * S_ + s];

    __shared__ float red[3][256];
    red[0][tid] = hd; red[1][tid] = gs; red[2][tid] = ds;
    __syncthreads();
    for (int o = 128; o > 0; o >>= 1) {
        if (tid < o) {
            red[0][tid] += red[0][tid + o];
            red[1][tid] += red[1][tid + o];
            red[2][tid] += red[2][tid + o];
        }
        __syncthreads();
    }
    if (tid == 0) {
        float gt = sigmoidf_(red[1][0] * (1.0f / S_) + b_gate[0]);
        float op = sigmoidf_(red[0][0] + b_dec[0]);
        float dp = sigmoidf_(red[2][0] + b_dd[0]);
        out[b] = op * gt + dp * (1.0f - gt);
    }
}

// ---------------- launch ------------------------------------------------------
extern "C" void kernel_launch(void* const* d_in, const int* in_sizes, int n_in,
                              void* d_out, int out_size)
{
    const float* v       = (const float*)d_in[0];
    const int*   cat     = (const int*)d_in[1];
    const float* W_enc   = (const float*)d_in[2];
    const float* b_enc   = (const float*)d_in[3];
    const float* Wx      = (const float*)d_in[4];
    const float* bx      = (const float*)d_in[5];
    const float* Wh      = (const float*)d_in[6];
    const float* bh      = (const float*)d_in[7];
    const float* cat_emb = (const float*)d_in[8];
    const float* W_dec   = (const float*)d_in[9];
    const float* b_dec   = (const float*)d_in[10];
    const float* proto   = (const float*)d_in[11];
    const float* W_dd    = (const float*)d_in[12];
    const float* b_dd    = (const float*)d_in[13];
    const float* W_gate  = (const float*)d_in[14];
    const float* b_gate  = (const float*)d_in[15];
    float* out = (float*)d_out;

    cat_normalize<<<1, 32>>>(cat);
    init_state<<<(B_ * H_ + 255) / 256, 256>>>();
    fuse_gemm<<<dim3(H_ / 128, R_ / 128), 256>>>(v, W_enc, b_enc, cat_emb);
    xg_gemm<<<dim3(G4_ / 128, R_ / 128), 256>>>(Wx, bx, bh);
    for (int s = 0; s < S_; s++)
        lstm_step<<<128, 256>>>(Wh, s);
    proto_kernel<<<R_, 128>>>(v, proto, W_dd);
    final_kernel<<<B_, 256>>>(v, W_dec, b_dec, W_gate, b_gate, b_dd, out);
}

// round 2
// speedup vs baseline: 1.0195x; 1.0195x over previous
#include <cuda_runtime.h>
#include <math.h>

#define B_  64
#define S_  64
#define F_  2048
#define H_  512
#define G4_ 2048
#define P_  20
#define R_  4096   // B*S

// ---------------- scratch (static device globals; no allocs) ----------------
__device__ float g_fuse[R_ * H_];        // [B*S, H]   8 MB
__device__ float g_xg[S_ * B_ * G4_];    // [S][B][4H] 32 MB
__device__ float g_hbuf[2][B_ * H_];     // double-buffered hidden state
__device__ float g_ddp[B_ * S_];         // per-(b,s) prototype partial
__device__ int   g_cat[B_];              // normalized category
__device__ unsigned g_bar_count;         // software grid barrier

__device__ __forceinline__ float sigmoidf_(float x) { return 1.0f / (1.0f + expf(-x)); }

// ---------------- category dtype normalization (int64 vs int32) + bar reset --
__global__ void cat_normalize(const int* __restrict__ w) {
    if (threadIdx.x == 0 && blockIdx.x == 0) {
        g_bar_count = 0u;
        bool oddzero = true, evenok = true;
        for (int i = 0; i < 32; i++) {
            int lo = w[2 * i], hi = w[2 * i + 1];
            if (hi != 0) oddzero = false;
            if (lo < 0 || lo > 2) evenok = false;
        }
        if (oddzero && evenok) {  // little-endian int64 layout
            const long long* c = (const long long*)w;
            for (int b = 0; b < B_; b++) g_cat[b] = (int)c[b];
        } else {                  // int32 layout
            for (int b = 0; b < B_; b++) g_cat[b] = w[b];
        }
    }
}

// ---------------- fuse = relu(v @ W_enc + b_enc) + cat_emb[cat] --------------
// M=4096, N=512, K=2048. 128x128 tile, BK=8, 256 threads, 8x8 micro.
__global__ __launch_bounds__(256) void fuse_gemm(
    const float* __restrict__ A, const float* __restrict__ W,
    const float* __restrict__ bias, const float* __restrict__ cat_emb)
{
    __shared__ float As[8][132];
    __shared__ float Bs[8][128];
    const int tid  = threadIdx.x;
    const int brow = blockIdx.y * 128;
    const int bcol = blockIdx.x * 128;
    const int a_r = tid >> 1, a_c = (tid & 1) * 4;
    const int b_r = tid >> 5, b_c = (tid & 31) * 4;
    const int trow = (tid >> 4) * 8, tcol = (tid & 15) * 8;
    const int K = F_, N = H_;

    float acc[8][8];
    #pragma unroll
    for (int i = 0; i < 8; i++)
        #pragma unroll
        for (int j = 0; j < 8; j++) acc[i][j] = 0.0f;

    for (int k0 = 0; k0 < K; k0 += 8) {
        float4 av = *reinterpret_cast<const float4*>(&A[(size_t)(brow + a_r) * K + k0 + a_c]);
        As[a_c + 0][a_r] = av.x; As[a_c + 1][a_r] = av.y;
        As[a_c + 2][a_r] = av.z; As[a_c + 3][a_r] = av.w;
        float4 bv = *reinterpret_cast<const float4*>(&W[(size_t)(k0 + b_r) * N + bcol + b_c]);
        *reinterpret_cast<float4*>(&Bs[b_r][b_c]) = bv;
        __syncthreads();
        #pragma unroll
        for (int k = 0; k < 8; k++) {
            float ar[8], br[8];
            #pragma unroll
            for (int i = 0; i < 8; i++) ar[i] = As[k][trow + i];
            #pragma unroll
            for (int j = 0; j < 8; j++) br[j] = Bs[k][tcol + j];
            #pragma unroll
            for (int i = 0; i < 8; i++)
                #pragma unroll
                for (int j = 0; j < 8; j++) acc[i][j] = fmaf(ar[i], br[j], acc[i][j]);
        }
        __syncthreads();
    }
    #pragma unroll
    for (int i = 0; i < 8; i++) {
        int r = brow + trow + i;
        int b = r >> 6;
        const float* ce = &cat_emb[g_cat[b] * H_];
        #pragma unroll
        for (int j = 0; j < 8; j++) {
            int n = bcol + tcol + j;
            float v = acc[i][j] + bias[n];
            v = fmaxf(v, 0.0f) + ce[n];
            g_fuse[(size_t)r * H_ + n] = v;
        }
    }
}

// ---------------- x_gates[s][b][g] = fuse @ Wx + (bx+bh) ---------------------
// M=4096, N=2048, K=512.
__global__ __launch_bounds__(256) void xg_gemm(
    const float* __restrict__ W, const float* __restrict__ bx,
    const float* __restrict__ bh)
{
    __shared__ float As[8][132];
    __shared__ float Bs[8][128];
    const int tid  = threadIdx.x;
    const int brow = blockIdx.y * 128;
    const int bcol = blockIdx.x * 128;
    const int a_r = tid >> 1, a_c = (tid & 1) * 4;
    const int b_r = tid >> 5, b_c = (tid & 31) * 4;
    const int trow = (tid >> 4) * 8, tcol = (tid & 15) * 8;
    const int K = H_, N = G4_;

    float acc[8][8];
    #pragma unroll
    for (int i = 0; i < 8; i++)
        #pragma unroll
        for (int j = 0; j < 8; j++) acc[i][j] = 0.0f;

    for (int k0 = 0; k0 < K; k0 += 8) {
        float4 av = *reinterpret_cast<const float4*>(&g_fuse[(size_t)(brow + a_r) * K + k0 + a_c]);
        As[a_c + 0][a_r] = av.x; As[a_c + 1][a_r] = av.y;
        As[a_c + 2][a_r] = av.z; As[a_c + 3][a_r] = av.w;
        float4 bv = *reinterpret_cast<const float4*>(&W[(size_t)(k0 + b_r) * N + bcol + b_c]);
        *reinterpret_cast<float4*>(&Bs[b_r][b_c]) = bv;
        __syncthreads();
        #pragma unroll
        for (int k = 0; k < 8; k++) {
            float ar[8], br[8];
            #pragma unroll
            for (int i = 0; i < 8; i++) ar[i] = As[k][trow + i];
            #pragma unroll
            for (int j = 0; j < 8; j++) br[j] = Bs[k][tcol + j];
            #pragma unroll
            for (int i = 0; i < 8; i++)
                #pragma unroll
                for (int j = 0; j < 8; j++) acc[i][j] = fmaf(ar[i], br[j], acc[i][j]);
        }
        __syncthreads();
    }
    #pragma unroll
    for (int i = 0; i < 8; i++) {
        int r = brow + trow + i;
        int bb = r >> 6, ss = r & 63;
        size_t base = ((size_t)(ss * B_ + bb)) * G4_;
        #pragma unroll
        for (int j = 0; j < 8; j++) {
            int n = bcol + tcol + j;
            g_xg[base + n] = acc[i][j] + bx[n] + bh[n];
        }
    }
}

// ---------------- persistent LSTM: all 64 steps in one kernel ----------------
// Grid: 128 blocks x 128 threads. Block owns hidden cols [4b, 4b+4) => 16 gate
// cols. Wh tile (512x16, 32KB) cached in shared once. c state lives in shared
// for the whole sequence. h double-buffered in global, __ldcg/__stcg (L1 is
// not coherent across the software grid barrier).
__global__ __launch_bounds__(128) void lstm_persist(const float* __restrict__ Wh)
{
    __shared__ float Whs[512][16];    // 32 KB
    __shared__ float As[2][16][68];   // 8.5 KB, double-buffered h chunks (transposed)
    __shared__ float Gs[64][17];      // gates exchange
    __shared__ float cs[64][4];       // cell state, block-private

    const int tid   = threadIdx.x;
    const int jbase = blockIdx.x * 4;
    const int tr = tid & 15;          // thread-row group: rows tr*4 .. tr*4+3
    const int tc = tid >> 4;          // thread-col group: cols tc*2, tc*2+1
    const int lr = tid >> 1;          // loader row 0..63
    const int lq = (tid & 1) * 2;     // loader quad base (k quads)

    // preload Wh tile: Whs[k][c], c = g*4+jl -> global col g*512 + jbase + jl
    for (int idx = tid; idx < 512 * 16; idx += 128) {
        int k = idx >> 4, c = idx & 15;
        Whs[k][c] = Wh[(size_t)k * G4_ + (c >> 2) * H_ + jbase + (c & 3)];
    }
    // init cell state
    if (tid < 64) { cs[tid][0] = 0.f; cs[tid][1] = 0.f; cs[tid][2] = 0.f; cs[tid][3] = 0.f; }
    __syncthreads();

    // xg column offsets for this thread's 2 cols (same gate, adjacent jl)
    const int c0 = tc * 2;
    const int xg_col = (c0 >> 2) * H_ + jbase + (c0 & 3);

    for (int s = 0; s < S_; s++) {
        const float* __restrict__ h_in = g_hbuf[s & 1];
        float* __restrict__ h_out      = g_hbuf[(s + 1) & 1];
        const float* __restrict__ xg_s = &g_xg[(size_t)s * B_ * G4_];

        float acc[4][2];
        #pragma unroll
        for (int i = 0; i < 4; i++) { acc[i][0] = 0.f; acc[i][1] = 0.f; }

        if (s > 0) {
            // prefetch chunk 0
            {
                const float* src = &h_in[lr * H_ + lq * 4];
                float4 v0 = __ldcg((const float4*)(src));
                float4 v1 = __ldcg((const float4*)(src + 4));
                As[0][lq * 4 + 0][lr] = v0.x; As[0][lq * 4 + 1][lr] = v0.y;
                As[0][lq * 4 + 2][lr] = v0.z; As[0][lq * 4 + 3][lr] = v0.w;
                As[0][lq * 4 + 4][lr] = v1.x; As[0][lq * 4 + 5][lr] = v1.y;
                As[0][lq * 4 + 6][lr] = v1.z; As[0][lq * 4 + 7][lr] = v1.w;
            }
            __syncthreads();
            int buf = 0;
            for (int kc = 0; kc < 32; kc++) {
                if (kc + 1 < 32) {
                    const float* src = &h_in[lr * H_ + (kc + 1) * 16 + lq * 4];
                    float4 v0 = __ldcg((const float4*)(src));
                    float4 v1 = __ldcg((const float4*)(src + 4));
                    float (*An)[68] = As[buf ^ 1];
                    An[lq * 4 + 0][lr] = v0.x; An[lq * 4 + 1][lr] = v0.y;
                    An[lq * 4 + 2][lr] = v0.z; An[lq * 4 + 3][lr] = v0.w;
                    An[lq * 4 + 4][lr] = v1.x; An[lq * 4 + 5][lr] = v1.y;
                    An[lq * 4 + 6][lr] = v1.z; An[lq * 4 + 7][lr] = v1.w;
                }
                const float (*Ac)[68] = As[buf];
                const int kb = kc * 16;
                #pragma unroll
                for (int k = 0; k < 16; k++) {
                    float4 a = *reinterpret_cast<const float4*>(&Ac[k][tr * 4]);
                    float2 b = *reinterpret_cast<const float2*>(&Whs[kb + k][c0]);
                    acc[0][0] = fmaf(a.x, b.x, acc[0][0]);
                    acc[1][0] = fmaf(a.y, b.x, acc[1][0]);
                    acc[2][0] = fmaf(a.z, b.x, acc[2][0]);
                    acc[3][0] = fmaf(a.w, b.x, acc[3][0]);
                    acc[0][1] = fmaf(a.x, b.y, acc[0][1]);
                    acc[1][1] = fmaf(a.y, b.y, acc[1][1]);
                    acc[2][1] = fmaf(a.z, b.y, acc[2][1]);
                    acc[3][1] = fmaf(a.w, b.y, acc[3][1]);
                }
                __syncthreads();
                buf ^= 1;
            }
        }

        // add precomputed input gates, stash into Gs
        #pragma unroll
        for (int i = 0; i < 4; i++) {
            int m = tr * 4 + i;
            float2 xg = *reinterpret_cast<const float2*>(&xg_s[(size_t)m * G4_ + xg_col]);
            Gs[m][c0 + 0] = acc[i][0] + xg.x;
            Gs[m][c0 + 1] = acc[i][1] + xg.y;
        }
        __syncthreads();

        // cell update: 256 (m, jl) pairs over 128 threads
        #pragma unroll
        for (int rep = 0; rep < 2; rep++) {
            int e = tid + rep * 128;
            int m = e >> 2, jl = e & 3;
            float iv = Gs[m][0 + jl];
            float fv = Gs[m][4 + jl];
            float ov = Gs[m][8 + jl];
            float gv = Gs[m][12 + jl];
            float co = cs[m][jl];
            float cn = sigmoidf_(fv) * co + sigmoidf_(iv) * tanhf(gv);
            float hn = sigmoidf_(ov) * cn;   // NOTE: no tanh on cell in this model
            cs[m][jl] = cn;
            __stcg(&h_out[m * H_ + jbase + jl], hn);
        }

        // grid barrier between steps (not after the last step)
        if (s + 1 < S_) {
            __syncthreads();
            __threadfence();
            if (tid == 0) {
                atomicAdd(&g_bar_count, 1u);
                unsigned target = (unsigned)((s + 1) * 128);
                while (*((volatile unsigned*)&g_bar_count) < target) { }
                __threadfence();
            }
            __syncthreads();
        } else {
            __syncthreads();   // protect Gs/cs before next loop iteration exit
        }
    }
}

// ---------------- prototype distances -> per-(b,s) W_dd partial --------------
__global__ __launch_bounds__(128) void proto_kernel(
    const float* __restrict__ v, const float* __restrict__ proto,
    const float* __restrict__ W_dd)
{
    const int r = blockIdx.x;          // b*S + s
    const int s = r & 63;
    const int tid = threadIdx.x;
    const float* vrow = &v[(size_t)r * F_];

    float acc[P_];
    #pragma unroll
    for (int p = 0; p < P_; p++) acc[p] = 0.0f;

    for (int f = tid; f < F_; f += 128) {
        float vv = vrow[f];
        #pragma unroll
        for (int p = 0; p < P_; p++) {
            float d = vv - proto[p * F_ + f];
            acc[p] = fmaf(d, d, acc[p]);
        }
    }
    #pragma unroll
    for (int p = 0; p < P_; p++) {
        float x = acc[p];
        #pragma unroll
        for (int o = 16; o > 0; o >>= 1) x += __shfl_down_sync(0xffffffffu, x, o);
        acc[p] = x;
    }
    __shared__ float wsum[4][P_];
    __shared__ float psum[P_];
    int wid = tid >> 5, lane = tid & 31;
    if (lane == 0)
        for (int p = 0; p < P_; p++) wsum[wid][p] = acc[p];
    __syncthreads();
    if (tid < P_) {
        float d = wsum[0][tid] + wsum[1][tid] + wsum[2][tid] + wsum[3][tid];
        float df = logf((d + 1.0f) / (d + 1e-8f));
        psum[tid] = df * W_dd[s * P_ + tid];
    }
    __syncthreads();
    if (tid == 0) {
        float t = 0.0f;
        for (int p = 0; p < P_; p++) t += psum[p];
        g_ddp[r] = t;
    }
}

// ---------------- final combine per batch ------------------------------------
__global__ __launch_bounds__(256) void final_kernel(
    const float* __restrict__ v, const float* __restrict__ W_dec,
    const float* __restrict__ b_dec, const float* __restrict__ W_gate,
    const float* __restrict__ b_gate, const float* __restrict__ b_dd,
    float* __restrict__ out)
{
    const int b = blockIdx.x;
    const int tid = threadIdx.x;

    float hd = 0.0f;
    for (int k = tid; k < H_; k += 256)
        hd += g_hbuf[0][b * H_ + k] * W_dec[k];   // after 64 steps h lives in buf 0

    float gs = 0.0f;
    const float* vb = &v[(size_t)b * S_ * F_];
    for (int idx = tid; idx < S_ * F_; idx += 256)
        gs += vb[idx] * W_gate[idx & (F_ - 1)];

    float ds = 0.0f;
    for (int s = tid; s < S_; s += 256)
        ds += g_ddp[b * S_ + s];

    __shared__ float red[3][256];
    red[0][tid] = hd; red[1][tid] = gs; red[2][tid] = ds;
    __syncthreads();
    for (int o = 128; o > 0; o >>= 1) {
        if (tid < o) {
            red[0][tid] += red[0][tid + o];
            red[1][tid] += red[1][tid + o];
            red[2][tid] += red[2][tid + o];
        }
        __syncthreads();
    }
    if (tid == 0) {
        float gt = sigmoidf_(red[1][0] * (1.0f / S_) + b_gate[0]);
        float op = sigmoidf_(red[0][0] + b_dec[0]);
        float dp = sigmoidf_(red[2][0] + b_dd[0]);
        out[b] = op * gt + dp * (1.0f - gt);
    }
}

// ---------------- launch ------------------------------------------------------
extern "C" void kernel_launch(void* const* d_in, const int* in_sizes, int n_in,
                              void* d_out, int out_size)
{
    const float* v       = (const float*)d_in[0];
    const int*   cat     = (const int*)d_in[1];
    const float* W_enc   = (const float*)d_in[2];
    const float* b_enc   = (const float*)d_in[3];
    const float* Wx      = (const float*)d_in[4];
    const float* bx      = (const float*)d_in[5];
    const float* Wh      = (const float*)d_in[6];
    const float* bh      = (const float*)d_in[7];
    const float* cat_emb = (const float*)d_in[8];
    const float* W_dec   = (const float*)d_in[9];
    const float* b_dec   = (const float*)d_in[10];
    const float* proto   = (const float*)d_in[11];
    const float* W_dd    = (const float*)d_in[12];
    const float* b_dd    = (const float*)d_in[13];
    const float* W_gate  = (const float*)d_in[14];
    const float* b_gate  = (const float*)d_in[15];
    float* out = (float*)d_out;

    cat_normalize<<<1, 32>>>(cat);
    fuse_gemm<<<dim3(H_ / 128, R_ / 128), 256>>>(v, W_enc, b_enc, cat_emb);
    xg_gemm<<<dim3(G4_ / 128, R_ / 128), 256>>>(Wx, bx, bh);
    lstm_persist<<<128, 128>>>(Wh);
    proto_kernel<<<R_, 128>>>(v, proto, W_dd);
    final_kernel<<<B_, 256>>>(v, W_dec, b_dec, W_gate, b_gate, b_dd, out);
}

// round 4
// speedup vs baseline: 1.4166x; 1.3895x over previous
#include <cuda_runtime.h>
#include <math.h>

#define B_  64
#define S_  64
#define F_  2048
#define H_  512
#define G4_ 2048
#define P_  20
#define R_  4096   // B*S

// ---------------- scratch (static device globals; no allocs) ----------------
__device__ float g_fuse[R_ * H_];        // [B*S, H]   8 MB
__device__ float g_xg[S_ * B_ * G4_];    // [S][B][4H] 32 MB
__device__ float g_hT[2][H_ * B_];       // hidden state, TRANSPOSED [k][batch], double-buffered
__device__ float g_ddp[B_ * S_];         // per-(b,s) prototype partial
__device__ int   g_cat[B_];              // normalized category
__device__ unsigned g_bar_count = 0u;    // monotonic ticket counter (never reset)

__device__ __forceinline__ float sigmoidf_(float x) { return 1.0f / (1.0f + expf(-x)); }

// Ticket barrier: robust to any starting value that is ≡0 (mod nblocks);
// each full kernel run advances the counter by steps*nblocks, preserving that.
__device__ __forceinline__ void grid_bar_arrive_wait() {
    unsigned ticket = atomicAdd(&g_bar_count, 1u);
    unsigned target = (ticket & ~127u) + 128u;
    while (*((volatile unsigned*)&g_bar_count) < target) __nanosleep(32);
}

// ---------------- category dtype normalization (int64 vs int32) -------------
__global__ void cat_normalize(const int* __restrict__ w) {
    if (threadIdx.x == 0 && blockIdx.x == 0) {
        bool oddzero = true, evenok = true;
        for (int i = 0; i < 32; i++) {
            int lo = w[2 * i], hi = w[2 * i + 1];
            if (hi != 0) oddzero = false;
            if (lo < 0 || lo > 2) evenok = false;
        }
        if (oddzero && evenok) {  // little-endian int64 layout
            const long long* c = (const long long*)w;
            for (int b = 0; b < B_; b++) g_cat[b] = (int)c[b];
        } else {                  // int32 layout
            for (int b = 0; b < B_; b++) g_cat[b] = w[b];
        }
    }
}

// ---------------- fuse = relu(v @ W_enc + b_enc) + cat_emb[cat] --------------
// M=4096, N=512, K=2048. 128x128 tile, BK=8, 256 threads, 8x8 micro.
__global__ __launch_bounds__(256) void fuse_gemm(
    const float* __restrict__ A, const float* __restrict__ W,
    const float* __restrict__ bias, const float* __restrict__ cat_emb)
{
    __shared__ float As[8][132];
    __shared__ float Bs[8][128];
    const int tid  = threadIdx.x;
    const int brow = blockIdx.y * 128;
    const int bcol = blockIdx.x * 128;
    const int a_r = tid >> 1, a_c = (tid & 1) * 4;
    const int b_r = tid >> 5, b_c = (tid & 31) * 4;
    const int trow = (tid >> 4) * 8, tcol = (tid & 15) * 8;
    const int K = F_, N = H_;

    float acc[8][8];
    #pragma unroll
    for (int i = 0; i < 8; i++)
        #pragma unroll
        for (int j = 0; j < 8; j++) acc[i][j] = 0.0f;

    for (int k0 = 0; k0 < K; k0 += 8) {
        float4 av = *reinterpret_cast<const float4*>(&A[(size_t)(brow + a_r) * K + k0 + a_c]);
        As[a_c + 0][a_r] = av.x; As[a_c + 1][a_r] = av.y;
        As[a_c + 2][a_r] = av.z; As[a_c + 3][a_r] = av.w;
        float4 bv = *reinterpret_cast<const float4*>(&W[(size_t)(k0 + b_r) * N + bcol + b_c]);
        *reinterpret_cast<float4*>(&Bs[b_r][b_c]) = bv;
        __syncthreads();
        #pragma unroll
        for (int k = 0; k < 8; k++) {
            float ar[8], br[8];
            #pragma unroll
            for (int i = 0; i < 8; i++) ar[i] = As[k][trow + i];
            #pragma unroll
            for (int j = 0; j < 8; j++) br[j] = Bs[k][tcol + j];
            #pragma unroll
            for (int i = 0; i < 8; i++)
                #pragma unroll
                for (int j = 0; j < 8; j++) acc[i][j] = fmaf(ar[i], br[j], acc[i][j]);
        }
        __syncthreads();
    }
    #pragma unroll
    for (int i = 0; i < 8; i++) {
        int r = brow + trow + i;
        int b = r >> 6;
        const float* ce = &cat_emb[g_cat[b] * H_];
        #pragma unroll
        for (int j = 0; j < 8; j++) {
            int n = bcol + tcol + j;
            float v = acc[i][j] + bias[n];
            v = fmaxf(v, 0.0f) + ce[n];
            g_fuse[(size_t)r * H_ + n] = v;
        }
    }
}

// ---------------- x_gates[s][b][g] = fuse @ Wx + (bx+bh) ---------------------
// M=4096, N=2048, K=512.
__global__ __launch_bounds__(256) void xg_gemm(
    const float* __restrict__ W, const float* __restrict__ bx,
    const float* __restrict__ bh)
{
    __shared__ float As[8][132];
    __shared__ float Bs[8][128];
    const int tid  = threadIdx.x;
    const int brow = blockIdx.y * 128;
    const int bcol = blockIdx.x * 128;
    const int a_r = tid >> 1, a_c = (tid & 1) * 4;
    const int b_r = tid >> 5, b_c = (tid & 31) * 4;
    const int trow = (tid >> 4) * 8, tcol = (tid & 15) * 8;
    const int K = H_, N = G4_;

    float acc[8][8];
    #pragma unroll
    for (int i = 0; i < 8; i++)
        #pragma unroll
        for (int j = 0; j < 8; j++) acc[i][j] = 0.0f;

    for (int k0 = 0; k0 < K; k0 += 8) {
        float4 av = *reinterpret_cast<const float4*>(&g_fuse[(size_t)(brow + a_r) * K + k0 + a_c]);
        As[a_c + 0][a_r] = av.x; As[a_c + 1][a_r] = av.y;
        As[a_c + 2][a_r] = av.z; As[a_c + 3][a_r] = av.w;
        float4 bv = *reinterpret_cast<const float4*>(&W[(size_t)(k0 + b_r) * N + bcol + b_c]);
        *reinterpret_cast<float4*>(&Bs[b_r][b_c]) = bv;
        __syncthreads();
        #pragma unroll
        for (int k = 0; k < 8; k++) {
            float ar[8], br[8];
            #pragma unroll
            for (int i = 0; i < 8; i++) ar[i] = As[k][trow + i];
            #pragma unroll
            for (int j = 0; j < 8; j++) br[j] = Bs[k][tcol + j];
            #pragma unroll
            for (int i = 0; i < 8; i++)
                #pragma unroll
                for (int j = 0; j < 8; j++) acc[i][j] = fmaf(ar[i], br[j], acc[i][j]);
        }
        __syncthreads();
    }
    #pragma unroll
    for (int i = 0; i < 8; i++) {
        int r = brow + trow + i;
        int bb = r >> 6, ss = r & 63;
        size_t base = ((size_t)(ss * B_ + bb)) * G4_;
        #pragma unroll
        for (int j = 0; j < 8; j++) {
            int n = bcol + tcol + j;
            g_xg[base + n] = acc[i][j] + bx[n] + bh[n];
        }
    }
}

// ---------------- persistent LSTM: all 64 steps in one kernel ----------------
// 128 blocks x 256 threads. Block owns h cols [4b,4b+4) => 16 gate cols.
// Wh tile (512x16) + FULL h tile (512x64, transposed) in dynamic shared.
// 256 threads = 128 output threads (4 rows x 2 cols) x 2 K-groups (K split).
// h exchanged through global TRANSPOSED buffers g_hT[buf][k][m] so the per-step
// reload is 32 fully-coalesced LDG.128 per thread issued back-to-back (MLP~32).
__global__ __launch_bounds__(256) void lstm_persist(const float* __restrict__ Wh)
{
    extern __shared__ float sm[];
    float* whs  = sm;                       // [512][16]  32 KB
    float* as_  = sm + 512 * 16;            // [512][64]  128 KB
    float* gs_  = as_ + 512 * 64;           // [64][17]   partial gates (kg 0 + xg)
    float* gs2_ = gs_ + 64 * 17;            // [64][17]   partial gates (kg 1)
    float* cs_  = gs2_ + 64 * 17;           // [4][64]    cell state

    const int tid   = threadIdx.x;
    const int jbase = blockIdx.x * 4;

    // compute mapping: kg = K half, t in [0,128): 4 rows x 2 cols
    const int kg  = tid >> 7;
    const int t   = tid & 127;
    const int tr4 = (t & 15) * 4;           // rows tr4..tr4+3
    const int c0  = (t >> 4) * 2;           // gate-cols c0, c0+1 (c0 even)
    const int gate = c0 >> 2;
    const int jl2  = c0 & 3;                // 0 or 2
    const int xg_col = gate * H_ + jbase + jl2;

    // cell-update mapping
    const int um = tid & 63;
    const int ujl = tid >> 6;

    // preload Wh tile: whs[k][c], c = g*4+jl -> global col g*512 + jbase + jl
    for (int idx = tid; idx < 512 * 16; idx += 256) {
        int k = idx >> 4, c = idx & 15;
        whs[idx] = Wh[(size_t)k * G4_ + (c >> 2) * H_ + jbase + (c & 3)];
    }
    cs_[tid] = 0.0f;   // 256 entries = all of [4][64]
    __syncthreads();

    for (int s = 0; s < S_; s++) {
        const float* __restrict__ hT_in = g_hT[s & 1];
        float* __restrict__ hT_out      = g_hT[(s + 1) & 1];
        const float* __restrict__ xg_s  = &g_xg[(size_t)s * B_ * G4_];

        // ---- load full h tile (transposed layout, perfectly coalesced) ----
        if (s > 0) {
            const float4* src = reinterpret_cast<const float4*>(hT_in);
            #pragma unroll
            for (int i = 0; i < 32; i++) {
                int f = tid + i * 256;              // float4 index 0..8191
                float4 v = __ldcg(&src[f]);
                *reinterpret_cast<float4*>(&as_[f * 4]) = v;  // as_[k][r4] = f*4
            }
        }
        __syncthreads();

        // ---- GEMM: 4 rows x 2 cols over this thread's K half ----
        float acc00 = 0.f, acc10 = 0.f, acc20 = 0.f, acc30 = 0.f;
        float acc01 = 0.f, acc11 = 0.f, acc21 = 0.f, acc31 = 0.f;
        if (s > 0) {
            const float* ap = &as_[(kg * 256) * 64 + tr4];
            const float* bp = &whs[(kg * 256) * 16 + c0];
            #pragma unroll 8
            for (int k = 0; k < 256; k++) {
                float4 a = *reinterpret_cast<const float4*>(ap); ap += 64;
                float2 b = *reinterpret_cast<const float2*>(bp); bp += 16;
                acc00 = fmaf(a.x, b.x, acc00);
                acc10 = fmaf(a.y, b.x, acc10);
                acc20 = fmaf(a.z, b.x, acc20);
                acc30 = fmaf(a.w, b.x, acc30);
                acc01 = fmaf(a.x, b.y, acc01);
                acc11 = fmaf(a.y, b.y, acc11);
                acc21 = fmaf(a.z, b.y, acc21);
                acc31 = fmaf(a.w, b.y, acc31);
            }
        }

        // ---- write partial gates (kg0 adds precomputed xg) ----
        {
            float a0[4] = {acc00, acc10, acc20, acc30};
            float a1[4] = {acc01, acc11, acc21, acc31};
            if (kg == 0) {
                #pragma unroll
                for (int i = 0; i < 4; i++) {
                    int m = tr4 + i;
                    float2 xv = *reinterpret_cast<const float2*>(
                        &xg_s[(size_t)m * G4_ + xg_col]);
                    gs_[m * 17 + c0]     = a0[i] + xv.x;
                    gs_[m * 17 + c0 + 1] = a1[i] + xv.y;
                }
            } else {
                #pragma unroll
                for (int i = 0; i < 4; i++) {
                    int m = tr4 + i;
                    gs2_[m * 17 + c0]     = a0[i];
                    gs2_[m * 17 + c0 + 1] = a1[i];
                }
            }
        }
        __syncthreads();

        // ---- fused cell update (one thread per (m, jl)) ----
        {
            float iv = gs_[um * 17 + 0  + ujl] + gs2_[um * 17 + 0  + ujl];
            float fv = gs_[um * 17 + 4  + ujl] + gs2_[um * 17 + 4  + ujl];
            float ov = gs_[um * 17 + 8  + ujl] + gs2_[um * 17 + 8  + ujl];
            float gv = gs_[um * 17 + 12 + ujl] + gs2_[um * 17 + 12 + ujl];
            float co = cs_[ujl * 64 + um];
            float cn = sigmoidf_(fv) * co + sigmoidf_(iv) * tanhf(gv);
            float hn = sigmoidf_(ov) * cn;   // NOTE: no tanh on cell in this model
            cs_[ujl * 64 + um] = cn;
            __stcg(&hT_out[(jbase + ujl) * B_ + um], hn);
        }

        // ---- grid barrier between steps ----
        if (s + 1 < S_) {
            __threadfence();
            __syncthreads();
            if (tid == 0) {
                grid_bar_arrive_wait();
                __threadfence();
            }
            __syncthreads();
        }
    }
}

// ---------------- prototype distances -> per-(b,s) W_dd partial --------------
__global__ __launch_bounds__(128) void proto_kernel(
    const float* __restrict__ v, const float* __restrict__ proto,
    const float* __restrict__ W_dd)
{
    const int r = blockIdx.x;          // b*S + s
    const int s = r & 63;
    const int tid = threadIdx.x;
    const float* vrow = &v[(size_t)r * F_];

    float acc[P_];
    #pragma unroll
    for (int p = 0; p < P_; p++) acc[p] = 0.0f;

    for (int f = tid; f < F_; f += 128) {
        float vv = vrow[f];
        #pragma unroll
        for (int p = 0; p < P_; p++) {
            float d = vv - proto[p * F_ + f];
            acc[p] = fmaf(d, d, acc[p]);
        }
    }
    #pragma unroll
    for (int p = 0; p < P_; p++) {
        float x = acc[p];
        #pragma unroll
        for (int o = 16; o > 0; o >>= 1) x += __shfl_down_sync(0xffffffffu, x, o);
        acc[p] = x;
    }
    __shared__ float wsum[4][P_];
    __shared__ float psum[P_];
    int wid = tid >> 5, lane = tid & 31;
    if (lane == 0)
        for (int p = 0; p < P_; p++) wsum[wid][p] = acc[p];
    __syncthreads();
    if (tid < P_) {
        float d = wsum[0][tid] + wsum[1][tid] + wsum[2][tid] + wsum[3][tid];
        float df = logf((d + 1.0f) / (d + 1e-8f));
        psum[tid] = df * W_dd[s * P_ + tid];
    }
    __syncthreads();
    if (tid == 0) {
        float t = 0.0f;
        for (int p = 0; p < P_; p++) t += psum[p];
        g_ddp[r] = t;
    }
}

// ---------------- final combine per batch ------------------------------------
__global__ __launch_bounds__(256) void final_kernel(
    const float* __restrict__ v, const float* __restrict__ W_dec,
    const float* __restrict__ b_dec, const float* __restrict__ W_gate,
    const float* __restrict__ b_gate, const float* __restrict__ b_dd,
    float* __restrict__ out)
{
    const int b = blockIdx.x;
    const int tid = threadIdx.x;

    float hd = 0.0f;
    for (int k = tid; k < H_; k += 256)
        hd += g_hT[0][k * B_ + b] * W_dec[k];   // after 64 steps h lives in buf 0

    float gs = 0.0f;
    const float* vb = &v[(size_t)b * S_ * F_];
    for (int idx = tid; idx < S_ * F_; idx += 256)
        gs += vb[idx] * W_gate[idx & (F_ - 1)];

    float ds = 0.0f;
    for (int s = tid; s < S_; s += 256)
        ds += g_ddp[b * S_ + s];

    __shared__ float red[3][256];
    red[0][tid] = hd; red[1][tid] = gs; red[2][tid] = ds;
    __syncthreads();
    for (int o = 128; o > 0; o >>= 1) {
        if (tid < o) {
            red[0][tid] += red[0][tid + o];
            red[1][tid] += red[1][tid + o];
            red[2][tid] += red[2][tid + o];
        }
        __syncthreads();
    }
    if (tid == 0) {
        float gt = sigmoidf_(red[1][0] * (1.0f / S_) + b_gate[0]);
        float op = sigmoidf_(red[0][0] + b_dec[0]);
        float dp = sigmoidf_(red[2][0] + b_dd[0]);
        out[b] = op * gt + dp * (1.0f - gt);
    }
}

// ---------------- launch ------------------------------------------------------
extern "C" void kernel_launch(void* const* d_in, const int* in_sizes, int n_in,
                              void* d_out, int out_size)
{
    const float* v       = (const float*)d_in[0];
    const int*   cat     = (const int*)d_in[1];
    const float* W_enc   = (const float*)d_in[2];
    const float* b_enc   = (const float*)d_in[3];
    const float* Wx      = (const float*)d_in[4];
    const float* bx      = (const float*)d_in[5];
    const float* Wh      = (const float*)d_in[6];
    const float* bh      = (const float*)d_in[7];
    const float* cat_emb = (const float*)d_in[8];
    const float* W_dec   = (const float*)d_in[9];
    const float* b_dec   = (const float*)d_in[10];
    const float* proto   = (const float*)d_in[11];
    const float* W_dd    = (const float*)d_in[12];
    const float* b_dd    = (const float*)d_in[13];
    const float* W_gate  = (const float*)d_in[14];
    const float* b_gate  = (const float*)d_in[15];
    float* out = (float*)d_out;

    const int lstm_smem = (512 * 16 + 512 * 64 + 64 * 17 * 2 + 4 * 64) * 4;
    cudaFuncSetAttribute(lstm_persist, cudaFuncAttributeMaxDynamicSharedMemorySize,
                         lstm_smem);

    cat_normalize<<<1, 32>>>(cat);
    fuse_gemm<<<dim3(H_ / 128, R_ / 128), 256>>>(v, W_enc, b_enc, cat_emb);
    xg_gemm<<<dim3(G4_ / 128, R_ / 128), 256>>>(Wx, bx, bh);
    lstm_persist<<<128, 256, lstm_smem>>>(Wh);
    proto_kernel<<<R_, 128>>>(v, proto, W_dd);
    final_kernel<<<B_, 256>>>(v, W_dec, b_dec, W_gate, b_gate, b_dd, out);
}

// round 5
// speedup vs baseline: 1.5531x; 1.0964x over previous
#include <cuda_runtime.h>
#include <math.h>

#define B_  64
#define S_  64
#define F_  2048
#define H_  512
#define G4_ 2048
#define P_  20
#define R_  4096   // B*S

// ---------------- scratch (static device globals; no allocs) ----------------
__device__ float g_fuse[R_ * H_];        // [B*S, H]   8 MB
__device__ float g_xg[S_ * B_ * G4_];    // [S][B][4H] 32 MB
__device__ float g_hT[2][H_ * B_];       // hidden state, TRANSPOSED [k][batch], double-buffered
__device__ float g_ddp[B_ * S_];         // per-(b,s) prototype partial
__device__ int   g_cat[B_];              // normalized category
__device__ unsigned g_bar_count = 0u;    // monotonic ticket counter (never reset)

__device__ __forceinline__ float sigmoidf_(float x) { return 1.0f / (1.0f + expf(-x)); }

// Ticket barrier: robust to any starting value that is ≡0 (mod nblocks);
// each full kernel run advances the counter by steps*nblocks, preserving that.
__device__ __forceinline__ void grid_bar_arrive_wait() {
    unsigned ticket = atomicAdd(&g_bar_count, 1u);
    unsigned target = (ticket & ~127u) + 128u;
    while (*((volatile unsigned*)&g_bar_count) < target) __nanosleep(32);
}

// ---------------- category dtype normalization (int64 vs int32) -------------
__global__ void cat_normalize(const int* __restrict__ w) {
    if (threadIdx.x == 0 && blockIdx.x == 0) {
        bool oddzero = true, evenok = true;
        for (int i = 0; i < 32; i++) {
            int lo = w[2 * i], hi = w[2 * i + 1];
            if (hi != 0) oddzero = false;
            if (lo < 0 || lo > 2) evenok = false;
        }
        if (oddzero && evenok) {  // little-endian int64 layout
            const long long* c = (const long long*)w;
            for (int b = 0; b < B_; b++) g_cat[b] = (int)c[b];
        } else {                  // int32 layout
            for (int b = 0; b < B_; b++) g_cat[b] = w[b];
        }
    }
}

// ---------------- fuse = relu(v @ W_enc + b_enc) + cat_emb[cat] --------------
// M=4096, N=512, K=2048. 128x128 tile, BK=8, 256 threads, 8x8 micro.
__global__ __launch_bounds__(256) void fuse_gemm(
    const float* __restrict__ A, const float* __restrict__ W,
    const float* __restrict__ bias, const float* __restrict__ cat_emb)
{
    __shared__ float As[8][132];
    __shared__ float Bs[8][128];
    const int tid  = threadIdx.x;
    const int brow = blockIdx.y * 128;
    const int bcol = blockIdx.x * 128;
    const int a_r = tid >> 1, a_c = (tid & 1) * 4;
    const int b_r = tid >> 5, b_c = (tid & 31) * 4;
    const int trow = (tid >> 4) * 8, tcol = (tid & 15) * 8;
    const int K = F_, N = H_;

    float acc[8][8];
    #pragma unroll
    for (int i = 0; i < 8; i++)
        #pragma unroll
        for (int j = 0; j < 8; j++) acc[i][j] = 0.0f;

    for (int k0 = 0; k0 < K; k0 += 8) {
        float4 av = *reinterpret_cast<const float4*>(&A[(size_t)(brow + a_r) * K + k0 + a_c]);
        As[a_c + 0][a_r] = av.x; As[a_c + 1][a_r] = av.y;
        As[a_c + 2][a_r] = av.z; As[a_c + 3][a_r] = av.w;
        float4 bv = *reinterpret_cast<const float4*>(&W[(size_t)(k0 + b_r) * N + bcol + b_c]);
        *reinterpret_cast<float4*>(&Bs[b_r][b_c]) = bv;
        __syncthreads();
        #pragma unroll
        for (int k = 0; k < 8; k++) {
            float ar[8], br[8];
            #pragma unroll
            for (int i = 0; i < 8; i++) ar[i] = As[k][trow + i];
            #pragma unroll
            for (int j = 0; j < 8; j++) br[j] = Bs[k][tcol + j];
            #pragma unroll
            for (int i = 0; i < 8; i++)
                #pragma unroll
                for (int j = 0; j < 8; j++) acc[i][j] = fmaf(ar[i], br[j], acc[i][j]);
        }
        __syncthreads();
    }
    #pragma unroll
    for (int i = 0; i < 8; i++) {
        int r = brow + trow + i;
        int b = r >> 6;
        const float* ce = &cat_emb[g_cat[b] * H_];
        #pragma unroll
        for (int j = 0; j < 8; j++) {
            int n = bcol + tcol + j;
            float v = acc[i][j] + bias[n];
            v = fmaxf(v, 0.0f) + ce[n];
            g_fuse[(size_t)r * H_ + n] = v;
        }
    }
}

// ---------------- x_gates[s][b][g] = fuse @ Wx + (bx+bh) ---------------------
// M=4096, N=2048, K=512.
__global__ __launch_bounds__(256) void xg_gemm(
    const float* __restrict__ W, const float* __restrict__ bx,
    const float* __restrict__ bh)
{
    __shared__ float As[8][132];
    __shared__ float Bs[8][128];
    const int tid  = threadIdx.x;
    const int brow = blockIdx.y * 128;
    const int bcol = blockIdx.x * 128;
    const int a_r = tid >> 1, a_c = (tid & 1) * 4;
    const int b_r = tid >> 5, b_c = (tid & 31) * 4;
    const int trow = (tid >> 4) * 8, tcol = (tid & 15) * 8;
    const int K = H_, N = G4_;

    float acc[8][8];
    #pragma unroll
    for (int i = 0; i < 8; i++)
        #pragma unroll
        for (int j = 0; j < 8; j++) acc[i][j] = 0.0f;

    for (int k0 = 0; k0 < K; k0 += 8) {
        float4 av = *reinterpret_cast<const float4*>(&g_fuse[(size_t)(brow + a_r) * K + k0 + a_c]);
        As[a_c + 0][a_r] = av.x; As[a_c + 1][a_r] = av.y;
        As[a_c + 2][a_r] = av.z; As[a_c + 3][a_r] = av.w;
        float4 bv = *reinterpret_cast<const float4*>(&W[(size_t)(k0 + b_r) * N + bcol + b_c]);
        *reinterpret_cast<float4*>(&Bs[b_r][b_c]) = bv;
        __syncthreads();
        #pragma unroll
        for (int k = 0; k < 8; k++) {
            float ar[8], br[8];
            #pragma unroll
            for (int i = 0; i < 8; i++) ar[i] = As[k][trow + i];
            #pragma unroll
            for (int j = 0; j < 8; j++) br[j] = Bs[k][tcol + j];
            #pragma unroll
            for (int i = 0; i < 8; i++)
                #pragma unroll
                for (int j = 0; j < 8; j++) acc[i][j] = fmaf(ar[i], br[j], acc[i][j]);
        }
        __syncthreads();
    }
    #pragma unroll
    for (int i = 0; i < 8; i++) {
        int r = brow + trow + i;
        int bb = r >> 6, ss = r & 63;
        size_t base = ((size_t)(ss * B_ + bb)) * G4_;
        #pragma unroll
        for (int j = 0; j < 8; j++) {
            int n = bcol + tcol + j;
            g_xg[base + n] = acc[i][j] + bx[n] + bh[n];
        }
    }
}

// ---------------- persistent LSTM: all 64 steps in one kernel ----------------
// 128 blocks x 256 threads. Block owns h cols [4b,4b+4) => 16 gate cols.
// 256 threads = 4 K-quarters (128 k each) x 64 output threads (4 rows x 4 cols).
// Each quarter loads ONLY its 32KB slice of the h tile and syncs via a
// 64-thread named barrier -> load/compute pipelined per quarter.
__global__ __launch_bounds__(256) void lstm_persist(const float* __restrict__ Wh)
{
    extern __shared__ float sm[];
    float* whs = sm;                        // [512][16]     32 KB
    float* as_ = sm + 512 * 16;             // [512][64]     128 KB
    float* gs_ = as_ + 512 * 64;            // [4][64*17]    partial gates per kq
    float* cs_ = gs_ + 4 * 64 * 17;         // [64][4]       cell state

    const int tid   = threadIdx.x;
    const int jbase = blockIdx.x * 4;

    const int kq = tid >> 6;                // K-quarter 0..3
    const int t  = tid & 63;
    const int tr4 = (t & 15) * 4;           // rows tr4..tr4+3
    const int c4  = (t >> 4) * 4;           // gate-cols c4..c4+3

    // cell-update mapping: thread -> (m, jl) with jl fastest (coalesced xg)
    const int cm  = tid >> 2;
    const int cjl = tid & 3;

    // preload Wh tile: whs[k][c], c = g*4+jl -> global col g*512 + jbase + jl
    for (int idx = tid; idx < 512 * 16; idx += 256) {
        int k = idx >> 4, c = idx & 15;
        whs[idx] = Wh[(size_t)k * G4_ + (c >> 2) * H_ + jbase + (c & 3)];
    }
    cs_[tid] = 0.0f;   // 256 entries = all of [64][4]
    __syncthreads();

    for (int s = 0; s < S_; s++) {
        const float* __restrict__ hT_in = g_hT[s & 1];
        float* __restrict__ hT_out      = g_hT[(s + 1) & 1];
        const float* __restrict__ xg_s  = &g_xg[(size_t)s * B_ * G4_];

        float acc[4][4];
        #pragma unroll
        for (int i = 0; i < 4; i++)
            #pragma unroll
            for (int j = 0; j < 4; j++) acc[i][j] = 0.0f;

        if (s > 0) {
            // ---- load this quarter's h slice (32 KB), coalesced ----
            const float4* src = reinterpret_cast<const float4*>(hT_in) + kq * 2048;
            float4* dst = reinterpret_cast<float4*>(as_ + kq * 8192);
            #pragma unroll
            for (int i = 0; i < 32; i++) {
                int f = t + i * 64;
                dst[f] = __ldcg(&src[f]);
            }
            // quarter-local barrier (2 warps, 64 threads)
            asm volatile("bar.sync %0, 64;" :: "r"(1 + kq) : "memory");

            // ---- GEMM: 4 rows x 4 cols over this quarter's 128 k ----
            const float* ap = &as_[(kq * 128) * 64 + tr4];
            const float* bp = &whs[(kq * 128) * 16 + c4];
            #pragma unroll 4
            for (int k = 0; k < 128; k++) {
                float4 a = *reinterpret_cast<const float4*>(ap); ap += 64;
                float4 b = *reinterpret_cast<const float4*>(bp); bp += 16;
                acc[0][0] = fmaf(a.x, b.x, acc[0][0]);
                acc[1][0] = fmaf(a.y, b.x, acc[1][0]);
                acc[2][0] = fmaf(a.z, b.x, acc[2][0]);
                acc[3][0] = fmaf(a.w, b.x, acc[3][0]);
                acc[0][1] = fmaf(a.x, b.y, acc[0][1]);
                acc[1][1] = fmaf(a.y, b.y, acc[1][1]);
                acc[2][1] = fmaf(a.z, b.y, acc[2][1]);
                acc[3][1] = fmaf(a.w, b.y, acc[3][1]);
                acc[0][2] = fmaf(a.x, b.z, acc[0][2]);
                acc[1][2] = fmaf(a.y, b.z, acc[1][2]);
                acc[2][2] = fmaf(a.z, b.z, acc[2][2]);
                acc[3][2] = fmaf(a.w, b.z, acc[3][2]);
                acc[0][3] = fmaf(a.x, b.w, acc[0][3]);
                acc[1][3] = fmaf(a.y, b.w, acc[1][3]);
                acc[2][3] = fmaf(a.z, b.w, acc[2][3]);
                acc[3][3] = fmaf(a.w, b.w, acc[3][3]);
            }
        }

        // ---- write partial gates (stride 17; zeros at s==0 keep it uniform) --
        {
            float* gq = gs_ + kq * (64 * 17);
            #pragma unroll
            for (int i = 0; i < 4; i++) {
                #pragma unroll
                for (int j = 0; j < 4; j++)
                    gq[(tr4 + i) * 17 + c4 + j] = acc[i][j];
            }
        }
        __syncthreads();

        // ---- fused cell update (one thread per (m, jl)) ----
        {
            const int m = cm, jl = cjl;
            float gv[4];
            #pragma unroll
            for (int g = 0; g < 4; g++) {
                float x = xg_s[(size_t)m * G4_ + g * H_ + jbase + jl];
                int o = m * 17 + g * 4 + jl;
                x += gs_[o] + gs_[64 * 17 + o] + gs_[2 * 64 * 17 + o] + gs_[3 * 64 * 17 + o];
                gv[g] = x;
            }
            float co = cs_[m * 4 + jl];
            float cn = sigmoidf_(gv[1]) * co + sigmoidf_(gv[0]) * tanhf(gv[3]);
            float hn = sigmoidf_(gv[2]) * cn;   // NOTE: no tanh on cell in this model
            cs_[m * 4 + jl] = cn;
            __stcg(&hT_out[(jbase + jl) * B_ + m], hn);
        }

        // ---- grid barrier between steps ----
        if (s + 1 < S_) {
            __threadfence();
            __syncthreads();
            if (tid == 0) {
                grid_bar_arrive_wait();
                __threadfence();
            }
            __syncthreads();
        }
    }
}

// ---------------- prototype distances -> per-(b,s) W_dd partial --------------
__global__ __launch_bounds__(128) void proto_kernel(
    const float* __restrict__ v, const float* __restrict__ proto,
    const float* __restrict__ W_dd)
{
    const int r = blockIdx.x;          // b*S + s
    const int s = r & 63;
    const int tid = threadIdx.x;
    const float* vrow = &v[(size_t)r * F_];

    float acc[P_];
    #pragma unroll
    for (int p = 0; p < P_; p++) acc[p] = 0.0f;

    for (int f = tid; f < F_; f += 128) {
        float vv = vrow[f];
        #pragma unroll
        for (int p = 0; p < P_; p++) {
            float d = vv - proto[p * F_ + f];
            acc[p] = fmaf(d, d, acc[p]);
        }
    }
    #pragma unroll
    for (int p = 0; p < P_; p++) {
        float x = acc[p];
        #pragma unroll
        for (int o = 16; o > 0; o >>= 1) x += __shfl_down_sync(0xffffffffu, x, o);
        acc[p] = x;
    }
    __shared__ float wsum[4][P_];
    __shared__ float psum[P_];
    int wid = tid >> 5, lane = tid & 31;
    if (lane == 0)
        for (int p = 0; p < P_; p++) wsum[wid][p] = acc[p];
    __syncthreads();
    if (tid < P_) {
        float d = wsum[0][tid] + wsum[1][tid] + wsum[2][tid] + wsum[3][tid];
        float df = logf((d + 1.0f) / (d + 1e-8f));
        psum[tid] = df * W_dd[s * P_ + tid];
    }
    __syncthreads();
    if (tid == 0) {
        float t = 0.0f;
        for (int p = 0; p < P_; p++) t += psum[p];
        g_ddp[r] = t;
    }
}

// ---------------- final combine per batch ------------------------------------
__global__ __launch_bounds__(256) void final_kernel(
    const float* __restrict__ v, const float* __restrict__ W_dec,
    const float* __restrict__ b_dec, const float* __restrict__ W_gate,
    const float* __restrict__ b_gate, const float* __restrict__ b_dd,
    float* __restrict__ out)
{
    const int b = blockIdx.x;
    const int tid = threadIdx.x;

    float hd = 0.0f;
    for (int k = tid; k < H_; k += 256)
        hd += g_hT[0][k * B_ + b] * W_dec[k];   // after 64 steps h lives in buf 0

    float gs = 0.0f;
    const float* vb = &v[(size_t)b * S_ * F_];
    for (int idx = tid; idx < S_ * F_; idx += 256)
        gs += vb[idx] * W_gate[idx & (F_ - 1)];

    float ds = 0.0f;
    for (int s = tid; s < S_; s += 256)
        ds += g_ddp[b * S_ + s];

    __shared__ float red[3][256];
    red[0][tid] = hd; red[1][tid] = gs; red[2][tid] = ds;
    __syncthreads();
    for (int o = 128; o > 0; o >>= 1) {
        if (tid < o) {
            red[0][tid] += red[0][tid + o];
            red[1][tid] += red[1][tid + o];
            red[2][tid] += red[2][tid + o];
        }
        __syncthreads();
    }
    if (tid == 0) {
        float gt = sigmoidf_(red[1][0] * (1.0f / S_) + b_gate[0]);
        float op = sigmoidf_(red[0][0] + b_dec[0]);
        float dp = sigmoidf_(red[2][0] + b_dd[0]);
        out[b] = op * gt + dp * (1.0f - gt);
    }
}

// ---------------- launch ------------------------------------------------------
extern "C" void kernel_launch(void* const* d_in, const int* in_sizes, int n_in,
                              void* d_out, int out_size)
{
    const float* v       = (const float*)d_in[0];
    const int*   cat     = (const int*)d_in[1];
    const float* W_enc   = (const float*)d_in[2];
    const float* b_enc   = (const float*)d_in[3];
    const float* Wx      = (const float*)d_in[4];
    const float* bx      = (const float*)d_in[5];
    const float* Wh      = (const float*)d_in[6];
    const float* bh      = (const float*)d_in[7];
    const float* cat_emb = (const float*)d_in[8];
    const float* W_dec   = (const float*)d_in[9];
    const float* b_dec   = (const float*)d_in[10];
    const float* proto   = (const float*)d_in[11];
    const float* W_dd    = (const float*)d_in[12];
    const float* b_dd    = (const float*)d_in[13];
    const float* W_gate  = (const float*)d_in[14];
    const float* b_gate  = (const float*)d_in[15];
    float* out = (float*)d_out;

    const int lstm_smem = (512 * 16 + 512 * 64 + 4 * 64 * 17 + 64 * 4) * 4;
    cudaFuncSetAttribute(lstm_persist, cudaFuncAttributeMaxDynamicSharedMemorySize,
                         lstm_smem);

    cat_normalize<<<1, 32>>>(cat);
    fuse_gemm<<<dim3(H_ / 128, R_ / 128), 256>>>(v, W_enc, b_enc, cat_emb);
    xg_gemm<<<dim3(G4_ / 128, R_ / 128), 256>>>(Wx, bx, bh);
    lstm_persist<<<128, 256, lstm_smem>>>(Wh);
    proto_kernel<<<R_, 128>>>(v, proto, W_dd);
    final_kernel<<<B_, 256>>>(v, W_dec, b_dec, W_gate, b_gate, b_dd, out);
}